// round 5
// baseline (speedup 1.0000x reference)
#include <cuda_runtime.h>
#include <cuda_bf16.h>
#include <cstdint>

#define MAX_N 100000
#define MAX_E 1600000
#define D     128
#define SCAN_BS 1024

// ---------------- static device scratch ----------------
__device__ int   g_cnt [MAX_N];
__device__ int   g_off [MAX_N + 1];
__device__ int   g_cur [MAX_N];
__device__ int   g_csr [MAX_E];
__device__ int   g_bsum[256];
__device__ float g_dinv[MAX_N];
__device__ float g_G[(size_t)MAX_N * D];
__device__ float g_H[(size_t)MAX_N * D];

// ---------------- degree histogram ----------------
__global__ void k_hist(int* cnt, const int* __restrict__ dst, int E) {
    int e = blockIdx.x * blockDim.x + threadIdx.x;
    if (e < E) atomicAdd(&cnt[dst[e]], 1);
}

// ---------------- 3-pass exclusive scan of cnt -> off (+dinv fused) ----------------
__global__ void k_scan1(const int* __restrict__ cnt, int* __restrict__ off,
                        int* __restrict__ bsum, float* __restrict__ dinv, int N) {
    __shared__ int sm[SCAN_BS];
    int i = blockIdx.x * SCAN_BS + threadIdx.x;
    int v = (i < N) ? cnt[i] : 0;
    if (i < N) dinv[i] = rsqrtf((float)(v + 1));   // +1 self loop
    sm[threadIdx.x] = v;
    __syncthreads();
    #pragma unroll
    for (int s = 1; s < SCAN_BS; s <<= 1) {
        int t = (threadIdx.x >= s) ? sm[threadIdx.x - s] : 0;
        __syncthreads();
        sm[threadIdx.x] += t;
        __syncthreads();
    }
    if (i < N) off[i] = sm[threadIdx.x] - v;
    if (threadIdx.x == SCAN_BS - 1) bsum[blockIdx.x] = sm[threadIdx.x];
}

__global__ void k_scan2(int* bsum, int nb) {
    __shared__ int sm[256];
    int i = threadIdx.x;
    int v = (i < nb) ? bsum[i] : 0;
    sm[i] = v;
    __syncthreads();
    #pragma unroll
    for (int s = 1; s < 256; s <<= 1) {
        int t = (i >= s) ? sm[i - s] : 0;
        __syncthreads();
        sm[i] += t;
        __syncthreads();
    }
    if (i < nb) bsum[i] = sm[i] - v;
}

__global__ void k_scan3(int* __restrict__ off, int* __restrict__ cur,
                        const int* __restrict__ bsum, int N, int E) {
    int i = blockIdx.x * SCAN_BS + threadIdx.x;
    if (i < N) {
        int o = off[i] + bsum[blockIdx.x];
        off[i] = o;
        cur[i] = o;
        if (i == N - 1) off[N] = E;
    }
}

// ---------------- CSR fill ----------------
__global__ void k_fill(const int* __restrict__ src, const int* __restrict__ dst,
                       int* __restrict__ cur, int* __restrict__ csr, int E) {
    int e = blockIdx.x * blockDim.x + threadIdx.x;
    if (e < E) {
        int pos = atomicAdd(&cur[dst[e]], 1);
        csr[pos] = src[e];
    }
}

// ---------------- GEMM1:  G = X @ W  ----------------
#define GEMM_BM 64
#define GEMM_SMEM ((GEMM_BM + 128) * 128 * 4)

__global__ void __launch_bounds__(256)
k_gemm(const float* __restrict__ X, const float* __restrict__ W,
       float* __restrict__ G, int N) {
    extern __shared__ float sm[];
    float* xs = sm;
    float* ws = sm + GEMM_BM * 128;
    int tid  = threadIdx.x;
    int row0 = blockIdx.x * GEMM_BM;

    {
        const float4* Wv = (const float4*)W;
        float4* wsv = (float4*)ws;
        for (int i = tid; i < 128 * 32; i += 256) wsv[i] = Wv[i];
    }
    {
        float4* xsv = (float4*)xs;
        for (int i = tid; i < GEMM_BM * 32; i += 256) {
            int r = i >> 5, c = i & 31;
            int gr = row0 + r;
            float4 v = make_float4(0.f, 0.f, 0.f, 0.f);
            if (gr < N) v = ((const float4*)(X + (size_t)gr * D))[c];
            xsv[i] = v;
        }
    }
    __syncthreads();

    int tn = tid & 31;
    int tm = tid >> 5;
    const float4* xsv = (const float4*)xs;
    const float4* wsv = (const float4*)ws;

    float4 acc[8];
    #pragma unroll
    for (int r = 0; r < 8; r++) acc[r] = make_float4(0.f, 0.f, 0.f, 0.f);

    #pragma unroll 4
    for (int k4 = 0; k4 < 32; k4++) {
        float4 b0 = wsv[(4 * k4 + 0) * 32 + tn];
        float4 b1 = wsv[(4 * k4 + 1) * 32 + tn];
        float4 b2 = wsv[(4 * k4 + 2) * 32 + tn];
        float4 b3 = wsv[(4 * k4 + 3) * 32 + tn];
        #pragma unroll
        for (int r = 0; r < 8; r++) {
            float4 a = xsv[(tm * 8 + r) * 32 + k4];
            acc[r].x = fmaf(a.x, b0.x, fmaf(a.y, b1.x, fmaf(a.z, b2.x, fmaf(a.w, b3.x, acc[r].x))));
            acc[r].y = fmaf(a.x, b0.y, fmaf(a.y, b1.y, fmaf(a.z, b2.y, fmaf(a.w, b3.y, acc[r].y))));
            acc[r].z = fmaf(a.x, b0.z, fmaf(a.y, b1.z, fmaf(a.z, b2.z, fmaf(a.w, b3.z, acc[r].z))));
            acc[r].w = fmaf(a.x, b0.w, fmaf(a.y, b1.w, fmaf(a.z, b2.w, fmaf(a.w, b3.w, acc[r].w))));
        }
    }

    #pragma unroll
    for (int r = 0; r < 8; r++) {
        int gr = row0 + tm * 8 + r;
        if (gr < N)
            ((float4*)(G + (size_t)gr * D))[tn] = acc[r];
    }
}

// ---- fused gather1 + GEMM2: warp handles 2 nodes:
//   h = relu(dinv[i]*(dinv[i]*G[i] + sum dinv[s]*G[s]) + b1)  (regs -> smem stage)
//   G2[i] = h @ W2
#define FUSE_WARPS 8
#define FUSE_SMEM  (128 * 128 * 4 + FUSE_WARPS * 2 * 128 * 4)   // W2 64KB + staging 8KB

__global__ void __launch_bounds__(256)
k_gather_gemm(const float* __restrict__ G, const float* __restrict__ dinv,
              const float* __restrict__ b, const float* __restrict__ W2,
              float* __restrict__ G2,
              const int* __restrict__ off, const int* __restrict__ csr, int N) {
    extern __shared__ float sm[];
    float* ws = sm;                                  // [128][128] W2
    float* stage = sm + 128 * 128;                   // [FUSE_WARPS][2][128]
    int tid  = threadIdx.x;
    int lane = tid & 31;
    int wid  = tid >> 5;

    {   // stage W2
        const float4* Wv = (const float4*)W2;
        float4* wsv = (float4*)ws;
        for (int i = tid; i < 128 * 32; i += 256) wsv[i] = Wv[i];
    }
    __syncthreads();

    int wgl = blockIdx.x * FUSE_WARPS + wid;
    const float4* Gv = (const float4*)G;
    float* hs = stage + wid * 256;

    float4 h2[2];
    int n0 = 2 * wgl;

    #pragma unroll
    for (int t = 0; t < 2; t++) {
        int n = n0 + t;
        float4 acc = make_float4(0.f, 0.f, 0.f, 0.f);
        if (n < N) {
            float dw = dinv[n];
            float4 self = Gv[(size_t)n * 32 + lane];
            acc = make_float4(self.x * dw, self.y * dw, self.z * dw, self.w * dw);
            int e = off[n], end = off[n + 1];
            for (; e + 4 <= end; e += 4) {
                int s0 = csr[e], s1 = csr[e + 1], s2 = csr[e + 2], s3 = csr[e + 3];
                float d0 = dinv[s0], d1 = dinv[s1], d2 = dinv[s2], d3 = dinv[s3];
                float4 v0 = Gv[(size_t)s0 * 32 + lane];
                float4 v1 = Gv[(size_t)s1 * 32 + lane];
                float4 v2 = Gv[(size_t)s2 * 32 + lane];
                float4 v3 = Gv[(size_t)s3 * 32 + lane];
                acc.x += (v0.x * d0 + v1.x * d1) + (v2.x * d2 + v3.x * d3);
                acc.y += (v0.y * d0 + v1.y * d1) + (v2.y * d2 + v3.y * d3);
                acc.z += (v0.z * d0 + v1.z * d1) + (v2.z * d2 + v3.z * d3);
                acc.w += (v0.w * d0 + v1.w * d1) + (v2.w * d2 + v3.w * d3);
            }
            for (; e < end; e++) {
                int s = csr[e];
                float ds = dinv[s];
                float4 v = Gv[(size_t)s * 32 + lane];
                acc.x = fmaf(v.x, ds, acc.x); acc.y = fmaf(v.y, ds, acc.y);
                acc.z = fmaf(v.z, ds, acc.z); acc.w = fmaf(v.w, ds, acc.w);
            }
            float4 bb = ((const float4*)b)[lane];
            acc.x = fmaxf(fmaf(acc.x, dw, bb.x), 0.f);
            acc.y = fmaxf(fmaf(acc.y, dw, bb.y), 0.f);
            acc.z = fmaxf(fmaf(acc.z, dw, bb.z), 0.f);
            acc.w = fmaxf(fmaf(acc.w, dw, bb.w), 0.f);
        }
        h2[t] = acc;
    }

    // stage h rows for warp-uniform broadcast reads (all lanes participate)
    ((float4*)hs)[lane]      = h2[0];
    ((float4*)hs)[32 + lane] = h2[1];
    __syncwarp(0xFFFFFFFFu);

    // GEMM2: each lane computes 4 output cols for both nodes
    const float4* wsv = (const float4*)ws;
    const float4* hv  = (const float4*)hs;
    float4 o0 = make_float4(0.f, 0.f, 0.f, 0.f);
    float4 o1 = make_float4(0.f, 0.f, 0.f, 0.f);

    #pragma unroll 4
    for (int k4 = 0; k4 < 32; k4++) {
        float4 a0 = hv[k4];            // warp-uniform broadcast
        float4 a1 = hv[32 + k4];
        float4 w0 = wsv[(4 * k4 + 0) * 32 + lane];
        float4 w1 = wsv[(4 * k4 + 1) * 32 + lane];
        float4 w2 = wsv[(4 * k4 + 2) * 32 + lane];
        float4 w3 = wsv[(4 * k4 + 3) * 32 + lane];
        o0.x = fmaf(a0.x, w0.x, fmaf(a0.y, w1.x, fmaf(a0.z, w2.x, fmaf(a0.w, w3.x, o0.x))));
        o0.y = fmaf(a0.x, w0.y, fmaf(a0.y, w1.y, fmaf(a0.z, w2.y, fmaf(a0.w, w3.y, o0.y))));
        o0.z = fmaf(a0.x, w0.z, fmaf(a0.y, w1.z, fmaf(a0.z, w2.z, fmaf(a0.w, w3.z, o0.z))));
        o0.w = fmaf(a0.x, w0.w, fmaf(a0.y, w1.w, fmaf(a0.z, w2.w, fmaf(a0.w, w3.w, o0.w))));
        o1.x = fmaf(a1.x, w0.x, fmaf(a1.y, w1.x, fmaf(a1.z, w2.x, fmaf(a1.w, w3.x, o1.x))));
        o1.y = fmaf(a1.x, w0.y, fmaf(a1.y, w1.y, fmaf(a1.z, w2.y, fmaf(a1.w, w3.y, o1.y))));
        o1.z = fmaf(a1.x, w0.z, fmaf(a1.y, w1.z, fmaf(a1.z, w2.z, fmaf(a1.w, w3.z, o1.z))));
        o1.w = fmaf(a1.x, w0.w, fmaf(a1.y, w1.w, fmaf(a1.z, w2.w, fmaf(a1.w, w3.w, o1.w))));
    }

    if (n0 < N)     ((float4*)(G2 + (size_t)n0 * D))[lane]       = o0;
    if (n0 + 1 < N) ((float4*)(G2 + (size_t)(n0 + 1) * D))[lane] = o1;
}

// ---------- gather2: H[i] = dinv[i]*(dinv[i]*G2[i] + sum dinv[s]*G2[s]) + b2 ----------
__global__ void __launch_bounds__(256)
k_gather(const float* __restrict__ G, const float* __restrict__ dinv,
         const float* __restrict__ b, float* __restrict__ H,
         const int* __restrict__ off, const int* __restrict__ csr, int N) {
    int gtid = blockIdx.x * blockDim.x + threadIdx.x;
    int w    = gtid >> 5;
    int lane = gtid & 31;
    if (w >= N) return;

    const float4* Gv = (const float4*)G;
    float dw = dinv[w];
    float4 self = Gv[(size_t)w * 32 + lane];
    float4 acc  = make_float4(self.x * dw, self.y * dw, self.z * dw, self.w * dw);
    int e = off[w], end = off[w + 1];

    for (; e + 4 <= end; e += 4) {
        int s0 = csr[e], s1 = csr[e + 1], s2 = csr[e + 2], s3 = csr[e + 3];
        float d0 = dinv[s0], d1 = dinv[s1], d2 = dinv[s2], d3 = dinv[s3];
        float4 v0 = Gv[(size_t)s0 * 32 + lane];
        float4 v1 = Gv[(size_t)s1 * 32 + lane];
        float4 v2 = Gv[(size_t)s2 * 32 + lane];
        float4 v3 = Gv[(size_t)s3 * 32 + lane];
        acc.x += (v0.x * d0 + v1.x * d1) + (v2.x * d2 + v3.x * d3);
        acc.y += (v0.y * d0 + v1.y * d1) + (v2.y * d2 + v3.y * d3);
        acc.z += (v0.z * d0 + v1.z * d1) + (v2.z * d2 + v3.z * d3);
        acc.w += (v0.w * d0 + v1.w * d1) + (v2.w * d2 + v3.w * d3);
    }
    for (; e < end; e++) {
        int s = csr[e];
        float ds = dinv[s];
        float4 v = Gv[(size_t)s * 32 + lane];
        acc.x = fmaf(v.x, ds, acc.x); acc.y = fmaf(v.y, ds, acc.y);
        acc.z = fmaf(v.z, ds, acc.z); acc.w = fmaf(v.w, ds, acc.w);
    }

    float4 bb = ((const float4*)b)[lane];
    acc.x = fmaf(acc.x, dw, bb.x);
    acc.y = fmaf(acc.y, dw, bb.y);
    acc.z = fmaf(acc.z, dw, bb.z);
    acc.w = fmaf(acc.w, dw, bb.w);
    ((float4*)H)[(size_t)w * 32 + lane] = acc;
}

// ---------------- pair dot products ----------------
__global__ void __launch_bounds__(256)
k_pairs(const float* __restrict__ H, const int* __restrict__ pos,
        const int* __restrict__ neg, float* __restrict__ out, int P) {
    int gtid = blockIdx.x * blockDim.x + threadIdx.x;
    int w    = gtid >> 5;
    int lane = gtid & 31;
    if (w >= 2 * P) return;
    const int* pr = (w < P) ? pos : neg;
    int idx = (w < P) ? w : (w - P);
    int u = pr[2 * idx];
    int v = pr[2 * idx + 1];
    float4 a = ((const float4*)(H + (size_t)u * D))[lane];
    float4 c = ((const float4*)(H + (size_t)v * D))[lane];
    float s = a.x * c.x + a.y * c.y + a.z * c.z + a.w * c.w;
    #pragma unroll
    for (int o = 16; o; o >>= 1) s += __shfl_xor_sync(0xFFFFFFFFu, s, o);
    if (lane == 0) out[w] = s;
}

// ---------------- launch ----------------
template <typename T>
static inline T* symaddr(const void* sym) {
    void* p = nullptr;
    cudaGetSymbolAddress(&p, sym);
    return (T*)p;
}

extern "C" void kernel_launch(void* const* d_in, const int* in_sizes, int n_in,
                              void* d_out, int out_size) {
    const float* x  = (const float*)d_in[0];
    const float* W1 = (const float*)d_in[1];
    const float* b1 = (const float*)d_in[2];
    const float* W2 = (const float*)d_in[3];
    const float* b2 = (const float*)d_in[4];
    const int* eidx = (const int*)d_in[5];
    const int* ppos = (const int*)d_in[6];
    const int* pneg = (const int*)d_in[7];
    float* out = (float*)d_out;

    const int N = in_sizes[0] / D;
    const int E = in_sizes[5] / 2;
    const int P = in_sizes[6] / 2;
    const int* src = eidx;
    const int* dst = eidx + E;

    int*   cnt  = symaddr<int>(g_cnt);
    int*   off  = symaddr<int>(g_off);
    int*   cur  = symaddr<int>(g_cur);
    int*   csr  = symaddr<int>(g_csr);
    int*   bsum = symaddr<int>(g_bsum);
    float* dinv = symaddr<float>(g_dinv);
    float* G    = symaddr<float>(g_G);
    float* H    = symaddr<float>(g_H);

    // one-time setup (deterministic; identical on every call thereafter)
    static bool s_init = false;
    static cudaStream_t s_side;
    static cudaEvent_t  ev_fork, ev_join;
    if (!s_init) {
        cudaStreamCreateWithFlags(&s_side, cudaStreamNonBlocking);
        cudaEventCreateWithFlags(&ev_fork, cudaEventDisableTiming);
        cudaEventCreateWithFlags(&ev_join, cudaEventDisableTiming);
        cudaFuncSetAttribute(k_gemm, cudaFuncAttributeMaxDynamicSharedMemorySize, GEMM_SMEM);
        cudaFuncSetAttribute(k_gather_gemm, cudaFuncAttributeMaxDynamicSharedMemorySize, FUSE_SMEM);
        s_init = true;
    }

    const int T = 256;
    int gridE     = (E + T - 1) / T;
    int nbScan    = (N + SCAN_BS - 1) / SCAN_BS;
    int gridGemm  = (N + GEMM_BM - 1) / GEMM_BM;
    int nWarpsF   = (N + 1) / 2;
    int gridFuse  = (nWarpsF + FUSE_WARPS - 1) / FUSE_WARPS;
    int gridGath  = (int)(((long long)N * 32 + T - 1) / T);
    int gridPairs = (int)(((long long)2 * P * 32 + T - 1) / T);

    // fork: CSR build on side stream, concurrent with GEMM1
    cudaEventRecord(ev_fork, 0);
    cudaStreamWaitEvent(s_side, ev_fork, 0);

    cudaMemsetAsync(cnt, 0, (size_t)N * sizeof(int), s_side);
    k_hist <<<gridE, T, 0, s_side>>>(cnt, dst, E);
    k_scan1<<<nbScan, SCAN_BS, 0, s_side>>>(cnt, off, bsum, dinv, N);
    k_scan2<<<1, 256, 0, s_side>>>(bsum, nbScan);
    k_scan3<<<nbScan, SCAN_BS, 0, s_side>>>(off, cur, bsum, N, E);
    k_fill <<<gridE, T, 0, s_side>>>(src, dst, cur, csr, E);
    cudaEventRecord(ev_join, s_side);

    // main: GEMM1 (graph-independent), then join before fused stage
    k_gemm<<<gridGemm, T, GEMM_SMEM>>>(x, W1, G, N);
    cudaStreamWaitEvent(0, ev_join, 0);

    // fused gather1+GEMM2: reads G (=G1), writes H (=G2)
    k_gather_gemm<<<gridFuse, T, FUSE_SMEM>>>(G, dinv, b1, W2, H, off, csr, N);

    // gather2: reads H (=G2), writes G (=final embeddings)
    k_gather<<<gridGath, T>>>(H, dinv, b2, G, off, csr, N);

    // link prediction on final embeddings (G buffer)
    k_pairs<<<gridPairs, T>>>(G, ppos, pneg, out, P);
}

// round 6
// speedup vs baseline: 1.1424x; 1.1424x over previous
#include <cuda_runtime.h>
#include <cuda_bf16.h>
#include <cstdint>

#define MAX_N 100000
#define MAX_E 1600000
#define D     128
#define SCAN_BS 1024

// ---------------- static device scratch ----------------
__device__ int   g_cnt [MAX_N];
__device__ int   g_off [MAX_N + 1];
__device__ int   g_cur [MAX_N];
__device__ int   g_csr [MAX_E];
__device__ int   g_bsum[256];
__device__ float g_dinv[MAX_N];
__device__ float g_G [(size_t)MAX_N * D];   // G1 = X@W1
__device__ float g_H [(size_t)MAX_N * D];   // H1, then final embeddings
__device__ float g_G2[(size_t)MAX_N * D];   // G2 = H1@W2 (separate so gather1 can still read G1)

// ---------------- degree histogram ----------------
__global__ void k_hist(int* cnt, const int* __restrict__ dst, int E) {
    int e = blockIdx.x * blockDim.x + threadIdx.x;
    if (e < E) atomicAdd(&cnt[dst[e]], 1);
}

// ---------------- 3-pass exclusive scan of cnt -> off (+dinv fused) ----------------
__global__ void k_scan1(const int* __restrict__ cnt, int* __restrict__ off,
                        int* __restrict__ bsum, float* __restrict__ dinv, int N) {
    __shared__ int sm[SCAN_BS];
    int i = blockIdx.x * SCAN_BS + threadIdx.x;
    int v = (i < N) ? cnt[i] : 0;
    if (i < N) dinv[i] = rsqrtf((float)(v + 1));   // +1 self loop
    sm[threadIdx.x] = v;
    __syncthreads();
    #pragma unroll
    for (int s = 1; s < SCAN_BS; s <<= 1) {
        int t = (threadIdx.x >= s) ? sm[threadIdx.x - s] : 0;
        __syncthreads();
        sm[threadIdx.x] += t;
        __syncthreads();
    }
    if (i < N) off[i] = sm[threadIdx.x] - v;
    if (threadIdx.x == SCAN_BS - 1) bsum[blockIdx.x] = sm[threadIdx.x];
}

__global__ void k_scan2(int* bsum, int nb) {
    __shared__ int sm[256];
    int i = threadIdx.x;
    int v = (i < nb) ? bsum[i] : 0;
    sm[i] = v;
    __syncthreads();
    #pragma unroll
    for (int s = 1; s < 256; s <<= 1) {
        int t = (i >= s) ? sm[i - s] : 0;
        __syncthreads();
        sm[i] += t;
        __syncthreads();
    }
    if (i < nb) bsum[i] = sm[i] - v;
}

__global__ void k_scan3(int* __restrict__ off, int* __restrict__ cur,
                        const int* __restrict__ bsum, int N, int E) {
    int i = blockIdx.x * SCAN_BS + threadIdx.x;
    if (i < N) {
        int o = off[i] + bsum[blockIdx.x];
        off[i] = o;
        cur[i] = o;
        if (i == N - 1) off[N] = E;
    }
}

// ---------------- CSR fill ----------------
__global__ void k_fill(const int* __restrict__ src, const int* __restrict__ dst,
                       int* __restrict__ cur, int* __restrict__ csr, int E) {
    int e = blockIdx.x * blockDim.x + threadIdx.x;
    if (e < E) {
        int pos = atomicAdd(&cur[dst[e]], 1);
        csr[pos] = src[e];
    }
}

// ---------------- GEMM over row range [rowStart, rowEnd):  G = X @ W ----------------
#define GEMM_BM 64
#define GEMM_SMEM ((GEMM_BM + 128) * 128 * 4)

__global__ void __launch_bounds__(256)
k_gemm(const float* __restrict__ X, const float* __restrict__ W,
       float* __restrict__ G, int rowStart, int rowEnd) {
    extern __shared__ float sm[];
    float* xs = sm;
    float* ws = sm + GEMM_BM * 128;
    int tid  = threadIdx.x;
    int row0 = rowStart + blockIdx.x * GEMM_BM;

    {
        const float4* Wv = (const float4*)W;
        float4* wsv = (float4*)ws;
        for (int i = tid; i < 128 * 32; i += 256) wsv[i] = Wv[i];
    }
    {
        float4* xsv = (float4*)xs;
        for (int i = tid; i < GEMM_BM * 32; i += 256) {
            int r = i >> 5, c = i & 31;
            int gr = row0 + r;
            float4 v = make_float4(0.f, 0.f, 0.f, 0.f);
            if (gr < rowEnd) v = ((const float4*)(X + (size_t)gr * D))[c];
            xsv[i] = v;
        }
    }
    __syncthreads();

    int tn = tid & 31;
    int tm = tid >> 5;
    const float4* xsv = (const float4*)xs;
    const float4* wsv = (const float4*)ws;

    float4 acc[8];
    #pragma unroll
    for (int r = 0; r < 8; r++) acc[r] = make_float4(0.f, 0.f, 0.f, 0.f);

    #pragma unroll 4
    for (int k4 = 0; k4 < 32; k4++) {
        float4 b0 = wsv[(4 * k4 + 0) * 32 + tn];
        float4 b1 = wsv[(4 * k4 + 1) * 32 + tn];
        float4 b2 = wsv[(4 * k4 + 2) * 32 + tn];
        float4 b3 = wsv[(4 * k4 + 3) * 32 + tn];
        #pragma unroll
        for (int r = 0; r < 8; r++) {
            float4 a = xsv[(tm * 8 + r) * 32 + k4];
            acc[r].x = fmaf(a.x, b0.x, fmaf(a.y, b1.x, fmaf(a.z, b2.x, fmaf(a.w, b3.x, acc[r].x))));
            acc[r].y = fmaf(a.x, b0.y, fmaf(a.y, b1.y, fmaf(a.z, b2.y, fmaf(a.w, b3.y, acc[r].y))));
            acc[r].z = fmaf(a.x, b0.z, fmaf(a.y, b1.z, fmaf(a.z, b2.z, fmaf(a.w, b3.z, acc[r].z))));
            acc[r].w = fmaf(a.x, b0.w, fmaf(a.y, b1.w, fmaf(a.z, b2.w, fmaf(a.w, b3.w, acc[r].w))));
        }
    }

    #pragma unroll
    for (int r = 0; r < 8; r++) {
        int gr = row0 + tm * 8 + r;
        if (gr < rowEnd)
            ((float4*)(G + (size_t)gr * D))[tn] = acc[r];
    }
}

// ---------- CSR gather conv over node range [nStart, nEnd) ----------
template <bool RELU>
__global__ void __launch_bounds__(256)
k_gather(const float* __restrict__ G, const float* __restrict__ dinv,
         const float* __restrict__ b, float* __restrict__ H,
         const int* __restrict__ off, const int* __restrict__ csr,
         int nStart, int nEnd) {
    int gtid = blockIdx.x * blockDim.x + threadIdx.x;
    int w    = nStart + (gtid >> 5);
    int lane = gtid & 31;
    if (w >= nEnd) return;

    const float4* Gv = (const float4*)G;
    float dw = dinv[w];
    float4 self = Gv[(size_t)w * 32 + lane];
    float4 acc  = make_float4(self.x * dw, self.y * dw, self.z * dw, self.w * dw);
    int e = off[w], end = off[w + 1];

    for (; e + 4 <= end; e += 4) {
        int s0 = csr[e], s1 = csr[e + 1], s2 = csr[e + 2], s3 = csr[e + 3];
        float d0 = dinv[s0], d1 = dinv[s1], d2 = dinv[s2], d3 = dinv[s3];
        float4 v0 = Gv[(size_t)s0 * 32 + lane];
        float4 v1 = Gv[(size_t)s1 * 32 + lane];
        float4 v2 = Gv[(size_t)s2 * 32 + lane];
        float4 v3 = Gv[(size_t)s3 * 32 + lane];
        acc.x += (v0.x * d0 + v1.x * d1) + (v2.x * d2 + v3.x * d3);
        acc.y += (v0.y * d0 + v1.y * d1) + (v2.y * d2 + v3.y * d3);
        acc.z += (v0.z * d0 + v1.z * d1) + (v2.z * d2 + v3.z * d3);
        acc.w += (v0.w * d0 + v1.w * d1) + (v2.w * d2 + v3.w * d3);
    }
    for (; e < end; e++) {
        int s = csr[e];
        float ds = dinv[s];
        float4 v = Gv[(size_t)s * 32 + lane];
        acc.x = fmaf(v.x, ds, acc.x); acc.y = fmaf(v.y, ds, acc.y);
        acc.z = fmaf(v.z, ds, acc.z); acc.w = fmaf(v.w, ds, acc.w);
    }

    float4 bb = ((const float4*)b)[lane];
    acc.x = fmaf(acc.x, dw, bb.x);
    acc.y = fmaf(acc.y, dw, bb.y);
    acc.z = fmaf(acc.z, dw, bb.z);
    acc.w = fmaf(acc.w, dw, bb.w);
    if (RELU) {
        acc.x = fmaxf(acc.x, 0.f); acc.y = fmaxf(acc.y, 0.f);
        acc.z = fmaxf(acc.z, 0.f); acc.w = fmaxf(acc.w, 0.f);
    }
    ((float4*)H)[(size_t)w * 32 + lane] = acc;
}

// ---------------- pair dot products ----------------
__global__ void __launch_bounds__(256)
k_pairs(const float* __restrict__ H, const int* __restrict__ pos,
        const int* __restrict__ neg, float* __restrict__ out, int P) {
    int gtid = blockIdx.x * blockDim.x + threadIdx.x;
    int w    = gtid >> 5;
    int lane = gtid & 31;
    if (w >= 2 * P) return;
    const int* pr = (w < P) ? pos : neg;
    int idx = (w < P) ? w : (w - P);
    int u = pr[2 * idx];
    int v = pr[2 * idx + 1];
    float4 a = ((const float4*)(H + (size_t)u * D))[lane];
    float4 c = ((const float4*)(H + (size_t)v * D))[lane];
    float s = a.x * c.x + a.y * c.y + a.z * c.z + a.w * c.w;
    #pragma unroll
    for (int o = 16; o; o >>= 1) s += __shfl_xor_sync(0xFFFFFFFFu, s, o);
    if (lane == 0) out[w] = s;
}

// ---------------- launch ----------------
template <typename T>
static inline T* symaddr(const void* sym) {
    void* p = nullptr;
    cudaGetSymbolAddress(&p, sym);
    return (T*)p;
}

extern "C" void kernel_launch(void* const* d_in, const int* in_sizes, int n_in,
                              void* d_out, int out_size) {
    const float* x  = (const float*)d_in[0];
    const float* W1 = (const float*)d_in[1];
    const float* b1 = (const float*)d_in[2];
    const float* W2 = (const float*)d_in[3];
    const float* b2 = (const float*)d_in[4];
    const int* eidx = (const int*)d_in[5];
    const int* ppos = (const int*)d_in[6];
    const int* pneg = (const int*)d_in[7];
    float* out = (float*)d_out;

    const int N = in_sizes[0] / D;
    const int E = in_sizes[5] / 2;
    const int P = in_sizes[6] / 2;
    const int* src = eidx;
    const int* dst = eidx + E;

    int*   cnt  = symaddr<int>(g_cnt);
    int*   off  = symaddr<int>(g_off);
    int*   cur  = symaddr<int>(g_cur);
    int*   csr  = symaddr<int>(g_csr);
    int*   bsum = symaddr<int>(g_bsum);
    float* dinv = symaddr<float>(g_dinv);
    float* G    = symaddr<float>(g_G);
    float* H    = symaddr<float>(g_H);
    float* G2   = symaddr<float>(g_G2);

    static bool s_init = false;
    static cudaStream_t s_side;
    static cudaEvent_t  ev_fork, ev_join, ev_c0, ev_c1, ev_m2;
    if (!s_init) {
        cudaStreamCreateWithFlags(&s_side, cudaStreamNonBlocking);
        cudaEventCreateWithFlags(&ev_fork, cudaEventDisableTiming);
        cudaEventCreateWithFlags(&ev_join, cudaEventDisableTiming);
        cudaEventCreateWithFlags(&ev_c0,   cudaEventDisableTiming);
        cudaEventCreateWithFlags(&ev_c1,   cudaEventDisableTiming);
        cudaEventCreateWithFlags(&ev_m2,   cudaEventDisableTiming);
        cudaFuncSetAttribute(k_gemm, cudaFuncAttributeMaxDynamicSharedMemorySize, GEMM_SMEM);
        s_init = true;
    }

    const int T = 256;
    int gridE  = (E + T - 1) / T;
    int nbScan = (N + SCAN_BS - 1) / SCAN_BS;

    int Nc = (((N + 1) / 2 + GEMM_BM - 1) / GEMM_BM) * GEMM_BM;   // GEMM-aligned midpoint
    if (Nc > N) Nc = N;

    auto gGemm = [&](int r0, int r1) { return (r1 - r0 + GEMM_BM - 1) / GEMM_BM; };
    auto gGath = [&](int n0, int n1) {
        return (int)(((long long)(n1 - n0) * 32 + T - 1) / T);
    };
    int gridPairs = (int)(((long long)2 * P * 32 + T - 1) / T);

    // ---- fork: CSR build on side stream, concurrent with GEMM1 ----
    cudaEventRecord(ev_fork, 0);
    cudaStreamWaitEvent(s_side, ev_fork, 0);

    cudaMemsetAsync(cnt, 0, (size_t)N * sizeof(int), s_side);
    k_hist <<<gridE, T, 0, s_side>>>(cnt, dst, E);
    k_scan1<<<nbScan, SCAN_BS, 0, s_side>>>(cnt, off, bsum, dinv, N);
    k_scan2<<<1, 256, 0, s_side>>>(bsum, nbScan);
    k_scan3<<<nbScan, SCAN_BS, 0, s_side>>>(off, cur, bsum, N, E);
    k_fill <<<gridE, T, 0, s_side>>>(src, dst, cur, csr, E);
    cudaEventRecord(ev_join, s_side);

    // ---- main: GEMM1 (full), join CSR ----
    k_gemm<<<gGemm(0, N), T, GEMM_SMEM>>>(x, W1, G, 0, N);
    cudaStreamWaitEvent(0, ev_join, 0);

    // ---- pipelined gather1 (main) / GEMM2 (side), 2 chunks ----
    k_gather<true><<<gGath(0, Nc), T>>>(G, dinv, b1, H, off, csr, 0, Nc);
    cudaEventRecord(ev_c0, 0);
    k_gather<true><<<gGath(Nc, N), T>>>(G, dinv, b1, H, off, csr, Nc, N);
    cudaEventRecord(ev_c1, 0);

    cudaStreamWaitEvent(s_side, ev_c0, 0);
    k_gemm<<<gGemm(0, Nc), T, GEMM_SMEM, s_side>>>(H, W2, G2, 0, Nc);
    cudaStreamWaitEvent(s_side, ev_c1, 0);
    k_gemm<<<gGemm(Nc, N), T, GEMM_SMEM, s_side>>>(H, W2, G2, Nc, N);
    cudaEventRecord(ev_m2, s_side);

    // ---- main: gather2 (reads G2, writes H final), pairs ----
    cudaStreamWaitEvent(0, ev_m2, 0);
    k_gather<false><<<gGath(0, N), T>>>(G2, dinv, b2, H, off, csr, 0, N);
    k_pairs<<<gridPairs, T>>>(H, ppos, pneg, out, P);
}

// round 7
// speedup vs baseline: 1.2422x; 1.0874x over previous
#include <cuda_runtime.h>
#include <cuda_fp16.h>
#include <cstdint>

#define MAX_N 100000
#define MAX_E 1600000
#define D     128
#define SCAN_BS 1024

// ---------------- static device scratch ----------------
__device__ int     g_cnt [MAX_N];
__device__ int     g_off [MAX_N + 1];
__device__ int     g_cur [MAX_N];
__device__ int     g_csr [MAX_E];
__device__ int     g_bsum[256];
__device__ float   g_dinv[MAX_N];
__device__ __half2 g_A[(size_t)MAX_N * (D / 2)];   // half feature buffer (G1, later G2)
__device__ float   g_B[(size_t)MAX_N * D];         // fp32 H1; tail: reused as half final H

// ---------------- degree histogram ----------------
__global__ void k_hist(int* cnt, const int* __restrict__ dst, int E) {
    int e = blockIdx.x * blockDim.x + threadIdx.x;
    if (e < E) atomicAdd(&cnt[dst[e]], 1);
}

// ---------------- scan pass 1: per-block exclusive scan (+dinv fused) ----------------
__global__ void k_scan1(const int* __restrict__ cnt, int* __restrict__ off,
                        int* __restrict__ bsum, float* __restrict__ dinv, int N) {
    __shared__ int sm[SCAN_BS];
    int i = blockIdx.x * SCAN_BS + threadIdx.x;
    int v = (i < N) ? cnt[i] : 0;
    if (i < N) dinv[i] = rsqrtf((float)(v + 1));   // +1 self loop
    sm[threadIdx.x] = v;
    __syncthreads();
    #pragma unroll
    for (int s = 1; s < SCAN_BS; s <<= 1) {
        int t = (threadIdx.x >= s) ? sm[threadIdx.x - s] : 0;
        __syncthreads();
        sm[threadIdx.x] += t;
        __syncthreads();
    }
    if (i < N) off[i] = sm[threadIdx.x] - v;
    if (threadIdx.x == SCAN_BS - 1) bsum[blockIdx.x] = sm[threadIdx.x];
}

// ---------------- scan pass 2: add block base (bsum scanned redundantly per block) ----------------
__global__ void k_scan3(int* __restrict__ off, int* __restrict__ cur,
                        const int* __restrict__ bsum, int N, int E, int nb) {
    __shared__ int sb[256];
    int t = threadIdx.x;
    if (t < 256) sb[t] = (t < nb) ? bsum[t] : 0;
    __syncthreads();
    #pragma unroll
    for (int s = 1; s < 256; s <<= 1) {
        int v = 0;
        if (t < 256 && t >= s) v = sb[t - s];
        __syncthreads();
        if (t < 256) sb[t] += v;
        __syncthreads();
    }
    int base = (blockIdx.x == 0) ? 0 : sb[blockIdx.x - 1];
    int i = blockIdx.x * SCAN_BS + t;
    if (i < N) {
        int o = off[i] + base;
        off[i] = o;
        cur[i] = o;
        if (i == N - 1) off[N] = E;
    }
}

// ---------------- CSR fill ----------------
__global__ void k_fill(const int* __restrict__ src, const int* __restrict__ dst,
                       int* __restrict__ cur, int* __restrict__ csr, int E) {
    int e = blockIdx.x * blockDim.x + threadIdx.x;
    if (e < E) {
        int pos = atomicAdd(&cur[dst[e]], 1);
        csr[pos] = src[e];
    }
}

// ---------------- GEMM:  Gh = X @ W  (fp32 compute, half2 output) ----------------
#define GEMM_BM 64
#define GEMM_SMEM ((GEMM_BM + 128) * 128 * 4)

__global__ void __launch_bounds__(256)
k_gemm(const float* __restrict__ X, const float* __restrict__ W,
       __half2* __restrict__ Gh, int N) {
    extern __shared__ float sm[];
    float* xs = sm;
    float* ws = sm + GEMM_BM * 128;
    int tid  = threadIdx.x;
    int row0 = blockIdx.x * GEMM_BM;

    {
        const float4* Wv = (const float4*)W;
        float4* wsv = (float4*)ws;
        for (int i = tid; i < 128 * 32; i += 256) wsv[i] = Wv[i];
    }
    {
        float4* xsv = (float4*)xs;
        for (int i = tid; i < GEMM_BM * 32; i += 256) {
            int r = i >> 5, c = i & 31;
            int gr = row0 + r;
            float4 v = make_float4(0.f, 0.f, 0.f, 0.f);
            if (gr < N) v = ((const float4*)(X + (size_t)gr * D))[c];
            xsv[i] = v;
        }
    }
    __syncthreads();

    int tn = tid & 31;
    int tm = tid >> 5;
    const float4* xsv = (const float4*)xs;
    const float4* wsv = (const float4*)ws;

    float4 acc[8];
    #pragma unroll
    for (int r = 0; r < 8; r++) acc[r] = make_float4(0.f, 0.f, 0.f, 0.f);

    #pragma unroll 4
    for (int k4 = 0; k4 < 32; k4++) {
        float4 b0 = wsv[(4 * k4 + 0) * 32 + tn];
        float4 b1 = wsv[(4 * k4 + 1) * 32 + tn];
        float4 b2 = wsv[(4 * k4 + 2) * 32 + tn];
        float4 b3 = wsv[(4 * k4 + 3) * 32 + tn];
        #pragma unroll
        for (int r = 0; r < 8; r++) {
            float4 a = xsv[(tm * 8 + r) * 32 + k4];
            acc[r].x = fmaf(a.x, b0.x, fmaf(a.y, b1.x, fmaf(a.z, b2.x, fmaf(a.w, b3.x, acc[r].x))));
            acc[r].y = fmaf(a.x, b0.y, fmaf(a.y, b1.y, fmaf(a.z, b2.y, fmaf(a.w, b3.y, acc[r].y))));
            acc[r].z = fmaf(a.x, b0.z, fmaf(a.y, b1.z, fmaf(a.z, b2.z, fmaf(a.w, b3.z, acc[r].z))));
            acc[r].w = fmaf(a.x, b0.w, fmaf(a.y, b1.w, fmaf(a.z, b2.w, fmaf(a.w, b3.w, acc[r].w))));
        }
    }

    #pragma unroll
    for (int r = 0; r < 8; r++) {
        int gr = row0 + tm * 8 + r;
        if (gr < N) {
            __half2 h0 = __float22half2_rn(make_float2(acc[r].x, acc[r].y));
            __half2 h1 = __float22half2_rn(make_float2(acc[r].z, acc[r].w));
            uint2 packed;
            packed.x = *(unsigned*)&h0;
            packed.y = *(unsigned*)&h1;
            ((uint2*)(Gh + (size_t)gr * (D / 2)))[tn] = packed;
        }
    }
}

// ---------- CSR gather conv (half2 input, fp32 accumulate):
//   out[i] = [relu](dinv[i]*(dinv[i]*G[i] + sum dinv[s]*G[s]) + b)
//   OUT_HALF: write __half2 (final layer), else fp32 float4 ----------
__device__ __forceinline__ float4 ld_half4(const __half2* row, int lane) {
    uint2 raw = ((const uint2*)row)[lane];
    __half2 p0 = *(__half2*)&raw.x;
    __half2 p1 = *(__half2*)&raw.y;
    float2 f0 = __half22float2(p0);
    float2 f1 = __half22float2(p1);
    return make_float4(f0.x, f0.y, f1.x, f1.y);
}

template <bool RELU, bool OUT_HALF>
__global__ void __launch_bounds__(256)
k_gather(const __half2* __restrict__ G, const float* __restrict__ dinv,
         const float* __restrict__ b, void* __restrict__ Hout,
         const int* __restrict__ off, const int* __restrict__ csr, int N) {
    int gtid = blockIdx.x * blockDim.x + threadIdx.x;
    int w    = gtid >> 5;
    int lane = gtid & 31;
    if (w >= N) return;

    float dw = dinv[w];
    float4 self = ld_half4(G + (size_t)w * (D / 2), lane);
    float4 acc  = make_float4(self.x * dw, self.y * dw, self.z * dw, self.w * dw);
    int e = off[w], end = off[w + 1];

    for (; e + 4 <= end; e += 4) {
        int s0 = csr[e], s1 = csr[e + 1], s2 = csr[e + 2], s3 = csr[e + 3];
        float d0 = dinv[s0], d1 = dinv[s1], d2 = dinv[s2], d3 = dinv[s3];
        float4 v0 = ld_half4(G + (size_t)s0 * (D / 2), lane);
        float4 v1 = ld_half4(G + (size_t)s1 * (D / 2), lane);
        float4 v2 = ld_half4(G + (size_t)s2 * (D / 2), lane);
        float4 v3 = ld_half4(G + (size_t)s3 * (D / 2), lane);
        acc.x += (v0.x * d0 + v1.x * d1) + (v2.x * d2 + v3.x * d3);
        acc.y += (v0.y * d0 + v1.y * d1) + (v2.y * d2 + v3.y * d3);
        acc.z += (v0.z * d0 + v1.z * d1) + (v2.z * d2 + v3.z * d3);
        acc.w += (v0.w * d0 + v1.w * d1) + (v2.w * d2 + v3.w * d3);
    }
    for (; e < end; e++) {
        int s = csr[e];
        float ds = dinv[s];
        float4 v = ld_half4(G + (size_t)s * (D / 2), lane);
        acc.x = fmaf(v.x, ds, acc.x); acc.y = fmaf(v.y, ds, acc.y);
        acc.z = fmaf(v.z, ds, acc.z); acc.w = fmaf(v.w, ds, acc.w);
    }

    float4 bb = ((const float4*)b)[lane];
    acc.x = fmaf(acc.x, dw, bb.x);
    acc.y = fmaf(acc.y, dw, bb.y);
    acc.z = fmaf(acc.z, dw, bb.z);
    acc.w = fmaf(acc.w, dw, bb.w);
    if (RELU) {
        acc.x = fmaxf(acc.x, 0.f); acc.y = fmaxf(acc.y, 0.f);
        acc.z = fmaxf(acc.z, 0.f); acc.w = fmaxf(acc.w, 0.f);
    }
    if (OUT_HALF) {
        __half2 h0 = __float22half2_rn(make_float2(acc.x, acc.y));
        __half2 h1 = __float22half2_rn(make_float2(acc.z, acc.w));
        uint2 packed;
        packed.x = *(unsigned*)&h0;
        packed.y = *(unsigned*)&h1;
        ((uint2*)((__half2*)Hout + (size_t)w * (D / 2)))[lane] = packed;
    } else {
        ((float4*)Hout)[(size_t)w * 32 + lane] = acc;
    }
}

// ---------------- GEMM2 variant: fp32 input (H1) -> half2 output ----------------
// (same as k_gemm; X is fp32 — identical code path, reused)

// ---------------- pair dot products on half2 embeddings ----------------
__global__ void __launch_bounds__(256)
k_pairs(const __half2* __restrict__ H, const int* __restrict__ pos,
        const int* __restrict__ neg, float* __restrict__ out, int P) {
    int gtid = blockIdx.x * blockDim.x + threadIdx.x;
    int w    = gtid >> 5;
    int lane = gtid & 31;
    if (w >= 2 * P) return;
    const int* pr = (w < P) ? pos : neg;
    int idx = (w < P) ? w : (w - P);
    int u = pr[2 * idx];
    int v = pr[2 * idx + 1];
    float4 a = ld_half4(H + (size_t)u * (D / 2), lane);
    float4 c = ld_half4(H + (size_t)v * (D / 2), lane);
    float s = a.x * c.x + a.y * c.y + a.z * c.z + a.w * c.w;
    #pragma unroll
    for (int o = 16; o; o >>= 1) s += __shfl_xor_sync(0xFFFFFFFFu, s, o);
    if (lane == 0) out[w] = s;
}

// ---------------- launch ----------------
template <typename T>
static inline T* symaddr(const void* sym) {
    void* p = nullptr;
    cudaGetSymbolAddress(&p, sym);
    return (T*)p;
}

extern "C" void kernel_launch(void* const* d_in, const int* in_sizes, int n_in,
                              void* d_out, int out_size) {
    const float* x  = (const float*)d_in[0];
    const float* W1 = (const float*)d_in[1];
    const float* b1 = (const float*)d_in[2];
    const float* W2 = (const float*)d_in[3];
    const float* b2 = (const float*)d_in[4];
    const int* eidx = (const int*)d_in[5];
    const int* ppos = (const int*)d_in[6];
    const int* pneg = (const int*)d_in[7];
    float* out = (float*)d_out;

    const int N = in_sizes[0] / D;
    const int E = in_sizes[5] / 2;
    const int P = in_sizes[6] / 2;
    const int* src = eidx;
    const int* dst = eidx + E;

    int*     cnt  = symaddr<int>(g_cnt);
    int*     off  = symaddr<int>(g_off);
    int*     cur  = symaddr<int>(g_cur);
    int*     csr  = symaddr<int>(g_csr);
    int*     bsum = symaddr<int>(g_bsum);
    float*   dinv = symaddr<float>(g_dinv);
    __half2* A    = symaddr<__half2>(g_A);   // G1, then G2
    float*   B    = symaddr<float>(g_B);     // H1 (fp32), then final H (half)
    __half2* Bh   = (__half2*)B;

    static bool s_init = false;
    static cudaStream_t s_side;
    static cudaEvent_t  ev_fork, ev_join;
    if (!s_init) {
        cudaStreamCreateWithFlags(&s_side, cudaStreamNonBlocking);
        cudaEventCreateWithFlags(&ev_fork, cudaEventDisableTiming);
        cudaEventCreateWithFlags(&ev_join, cudaEventDisableTiming);
        cudaFuncSetAttribute(k_gemm, cudaFuncAttributeMaxDynamicSharedMemorySize, GEMM_SMEM);
        s_init = true;
    }

    const int T = 256;
    int gridE     = (E + T - 1) / T;
    int nbScan    = (N + SCAN_BS - 1) / SCAN_BS;
    int gridGemm  = (N + GEMM_BM - 1) / GEMM_BM;
    int gridGath  = (int)(((long long)N * 32 + T - 1) / T);
    int gridPairs = (int)(((long long)2 * P * 32 + T - 1) / T);

    // ---- fork: CSR build on side stream, concurrent with GEMM1 ----
    cudaEventRecord(ev_fork, 0);
    cudaStreamWaitEvent(s_side, ev_fork, 0);

    cudaMemsetAsync(cnt, 0, (size_t)N * sizeof(int), s_side);
    k_hist <<<gridE, T, 0, s_side>>>(cnt, dst, E);
    k_scan1<<<nbScan, SCAN_BS, 0, s_side>>>(cnt, off, bsum, dinv, N);
    k_scan3<<<nbScan, SCAN_BS, 0, s_side>>>(off, cur, bsum, N, E, nbScan);
    k_fill <<<gridE, T, 0, s_side>>>(src, dst, cur, csr, E);
    cudaEventRecord(ev_join, s_side);

    // ---- main: GEMM1 (X fp32 -> A half), join CSR ----
    k_gemm<<<gridGemm, T, GEMM_SMEM>>>(x, W1, A, N);
    cudaStreamWaitEvent(0, ev_join, 0);

    // gather1: A(half) -> B(fp32), relu
    k_gather<true, false><<<gridGath, T>>>(A, dinv, b1, B, off, csr, N);

    // GEMM2: B(fp32) -> A(half)
    k_gemm<<<gridGemm, T, GEMM_SMEM>>>(B, W2, A, N);

    // gather2: A(half) -> Bh(half), no relu
    k_gather<false, true><<<gridGath, T>>>(A, dinv, b2, Bh, off, csr, N);

    // pairs on half embeddings
    k_pairs<<<gridPairs, T>>>(Bh, ppos, pneg, out, P);
}

// round 11
// speedup vs baseline: 1.2898x; 1.0383x over previous
#include <cuda_runtime.h>
#include <cuda_fp16.h>
#include <mma.h>
#include <cstdint>

using namespace nvcuda;

#define MAX_N 100000
#define MAX_E 1600000
#define D     128
#define SCAN_BS 1024

// ---------------- static device scratch ----------------
__device__ int     g_cnt [MAX_N];
__device__ int     g_off [MAX_N + 1];
__device__ int     g_cur [MAX_N];
__device__ int     g_csr [MAX_E];
__device__ int     g_bsum[256];
__device__ float   g_dinv[MAX_N];
__device__ __half  g_W2h[D * D];
__device__ __half2 g_A[(size_t)MAX_N * (D / 2)];   // G1, later G2
__device__ __half2 g_B[(size_t)MAX_N * (D / 2)];   // H1, later final H

// ---------------- degree histogram ----------------
__global__ void k_hist(int* cnt, const int* __restrict__ dst, int E) {
    int e = blockIdx.x * blockDim.x + threadIdx.x;
    if (e < E) atomicAdd(&cnt[dst[e]], 1);
}

// ---------------- scan pass 1: per-block exclusive scan (+dinv fused) ----------------
__global__ void k_scan1(const int* __restrict__ cnt, int* __restrict__ off,
                        int* __restrict__ bsum, float* __restrict__ dinv, int N) {
    __shared__ int sm[SCAN_BS];
    int i = blockIdx.x * SCAN_BS + threadIdx.x;
    int v = (i < N) ? cnt[i] : 0;
    if (i < N) dinv[i] = rsqrtf((float)(v + 1));   // +1 self loop
    sm[threadIdx.x] = v;
    __syncthreads();
    #pragma unroll
    for (int s = 1; s < SCAN_BS; s <<= 1) {
        int t = (threadIdx.x >= s) ? sm[threadIdx.x - s] : 0;
        __syncthreads();
        sm[threadIdx.x] += t;
        __syncthreads();
    }
    if (i < N) off[i] = sm[threadIdx.x] - v;
    if (threadIdx.x == SCAN_BS - 1) bsum[blockIdx.x] = sm[threadIdx.x];
}

// ---------------- scan pass 2: add block base (bsum scanned redundantly per block) ----------------
__global__ void k_scan3(int* __restrict__ off, int* __restrict__ cur,
                        const int* __restrict__ bsum, int N, int E, int nb) {
    __shared__ int sb[256];
    int t = threadIdx.x;
    if (t < 256) sb[t] = (t < nb) ? bsum[t] : 0;
    __syncthreads();
    #pragma unroll
    for (int s = 1; s < 256; s <<= 1) {
        int v = 0;
        if (t < 256 && t >= s) v = sb[t - s];
        __syncthreads();
        if (t < 256) sb[t] += v;
        __syncthreads();
    }
    int base = (blockIdx.x == 0) ? 0 : sb[blockIdx.x - 1];
    int i = blockIdx.x * SCAN_BS + t;
    if (i < N) {
        int o = off[i] + base;
        off[i] = o;
        cur[i] = o;
        if (i == N - 1) off[N] = E;
    }
}

// ---------------- CSR fill ----------------
__global__ void k_fill(const int* __restrict__ src, const int* __restrict__ dst,
                       int* __restrict__ cur, int* __restrict__ csr, int E) {
    int e = blockIdx.x * blockDim.x + threadIdx.x;
    if (e < E) {
        int pos = atomicAdd(&cur[dst[e]], 1);
        csr[pos] = src[e];
    }
}

// ---------------- W2 fp32 -> fp16 ----------------
__global__ void k_w2h(const float* __restrict__ W, __half* __restrict__ Wh) {
    int i = blockIdx.x * blockDim.x + threadIdx.x;
    if (i < D * D) Wh[i] = __float2half(W[i]);
}

// ---------------- GEMM1:  Gh = X @ W  (fp32 SIMT, half2 output) ----------------
#define GEMM_BM 64
#define GEMM_SMEM ((GEMM_BM + 128) * 128 * 4)

__global__ void __launch_bounds__(256)
k_gemm(const float* __restrict__ X, const float* __restrict__ W,
       __half2* __restrict__ Gh, int N) {
    extern __shared__ float sm[];
    float* xs = sm;
    float* ws = sm + GEMM_BM * 128;
    int tid  = threadIdx.x;
    int row0 = blockIdx.x * GEMM_BM;

    {
        const float4* Wv = (const float4*)W;
        float4* wsv = (float4*)ws;
        for (int i = tid; i < 128 * 32; i += 256) wsv[i] = Wv[i];
    }
    {
        float4* xsv = (float4*)xs;
        for (int i = tid; i < GEMM_BM * 32; i += 256) {
            int r = i >> 5, c = i & 31;
            int gr = row0 + r;
            float4 v = make_float4(0.f, 0.f, 0.f, 0.f);
            if (gr < N) v = ((const float4*)(X + (size_t)gr * D))[c];
            xsv[i] = v;
        }
    }
    __syncthreads();

    int tn = tid & 31;
    int tm = tid >> 5;
    const float4* xsv = (const float4*)xs;
    const float4* wsv = (const float4*)ws;

    float4 acc[8];
    #pragma unroll
    for (int r = 0; r < 8; r++) acc[r] = make_float4(0.f, 0.f, 0.f, 0.f);

    #pragma unroll 4
    for (int k4 = 0; k4 < 32; k4++) {
        float4 b0 = wsv[(4 * k4 + 0) * 32 + tn];
        float4 b1 = wsv[(4 * k4 + 1) * 32 + tn];
        float4 b2 = wsv[(4 * k4 + 2) * 32 + tn];
        float4 b3 = wsv[(4 * k4 + 3) * 32 + tn];
        #pragma unroll
        for (int r = 0; r < 8; r++) {
            float4 a = xsv[(tm * 8 + r) * 32 + k4];
            acc[r].x = fmaf(a.x, b0.x, fmaf(a.y, b1.x, fmaf(a.z, b2.x, fmaf(a.w, b3.x, acc[r].x))));
            acc[r].y = fmaf(a.x, b0.y, fmaf(a.y, b1.y, fmaf(a.z, b2.y, fmaf(a.w, b3.y, acc[r].y))));
            acc[r].z = fmaf(a.x, b0.z, fmaf(a.y, b1.z, fmaf(a.z, b2.z, fmaf(a.w, b3.z, acc[r].z))));
            acc[r].w = fmaf(a.x, b0.w, fmaf(a.y, b1.w, fmaf(a.z, b2.w, fmaf(a.w, b3.w, acc[r].w))));
        }
    }

    #pragma unroll
    for (int r = 0; r < 8; r++) {
        int gr = row0 + tm * 8 + r;
        if (gr < N) {
            __half2 h0 = __float22half2_rn(make_float2(acc[r].x, acc[r].y));
            __half2 h1 = __float22half2_rn(make_float2(acc[r].z, acc[r].w));
            uint2 packed;
            packed.x = *(unsigned*)&h0;
            packed.y = *(unsigned*)&h1;
            ((uint2*)(Gh + (size_t)gr * (D / 2)))[tn] = packed;
        }
    }
}

// ---------------- GEMM2 (tensor cores): Out = Ah @ Wh,  half in/out, fp32 accum ----------------
// 256 threads = 8 warps; 128 rows per CTA (16 rows per warp); full 128 cols.
__global__ void __launch_bounds__(256)
k_gemm2_wmma(const __half* __restrict__ Ah, const __half* __restrict__ Wh,
             __half* __restrict__ Out, int N) {
    __shared__ __half ws[D * D];                 // 32 KB
    __shared__ float scratch[8][16 * 16];        // 8 KB (per-warp store tile)
    int tid  = threadIdx.x;
    int wid  = tid >> 5;
    int lane = tid & 31;

    // stage W2 (half): 16384 halves = 2048 float4
    for (int i = tid; i < D * D / 8; i += 256)
        ((float4*)ws)[i] = ((const float4*)Wh)[i];
    __syncthreads();

    int row0 = blockIdx.x * 128 + wid * 16;
    if (row0 >= N) return;   // N % 16 == 0: warp tiles never straddle N

    wmma::fragment<wmma::accumulator, 16, 16, 16, float> c[8];
    #pragma unroll
    for (int n = 0; n < 8; n++) wmma::fill_fragment(c[n], 0.0f);

    #pragma unroll
    for (int k = 0; k < 8; k++) {
        wmma::fragment<wmma::matrix_a, 16, 16, 16, __half, wmma::row_major> a;
        wmma::load_matrix_sync(a, Ah + (size_t)row0 * D + k * 16, D);
        #pragma unroll
        for (int n = 0; n < 8; n++) {
            wmma::fragment<wmma::matrix_b, 16, 16, 16, __half, wmma::row_major> bf;
            wmma::load_matrix_sync(bf, ws + (k * 16) * D + n * 16, D);
            wmma::mma_sync(c[n], a, bf, c[n]);
        }
    }

    // store: f32 frag -> smem -> half global
    #pragma unroll
    for (int n = 0; n < 8; n++) {
        wmma::store_matrix_sync(scratch[wid], c[n], 16, wmma::mem_row_major);
        __syncwarp();
        #pragma unroll
        for (int j = 0; j < 8; j++) {
            int e = lane + j * 32;        // 0..255
            int r = e >> 4, col = e & 15;
            Out[(size_t)(row0 + r) * D + n * 16 + col] = __float2half(scratch[wid][e]);
        }
        __syncwarp();
    }
}

// ---------- CSR gather conv (half2 in, fp32 accumulate, half2 out) ----------
__device__ __forceinline__ float4 ld_half4(const __half2* row, int lane) {
    uint2 raw = ((const uint2*)row)[lane];
    __half2 p0 = *(__half2*)&raw.x;
    __half2 p1 = *(__half2*)&raw.y;
    float2 f0 = __half22float2(p0);
    float2 f1 = __half22float2(p1);
    return make_float4(f0.x, f0.y, f1.x, f1.y);
}

template <bool RELU>
__global__ void __launch_bounds__(256)
k_gather(const __half2* __restrict__ G, const float* __restrict__ dinv,
         const float* __restrict__ b, __half2* __restrict__ Hout,
         const int* __restrict__ off, const int* __restrict__ csr, int N) {
    int gtid = blockIdx.x * blockDim.x + threadIdx.x;
    int w    = gtid >> 5;
    int lane = gtid & 31;
    if (w >= N) return;

    float dw = dinv[w];
    float4 self = ld_half4(G + (size_t)w * (D / 2), lane);
    float4 acc  = make_float4(self.x * dw, self.y * dw, self.z * dw, self.w * dw);
    int e = off[w], end = off[w + 1];

    for (; e + 4 <= end; e += 4) {
        int s0 = csr[e], s1 = csr[e + 1], s2 = csr[e + 2], s3 = csr[e + 3];
        float d0 = dinv[s0], d1 = dinv[s1], d2 = dinv[s2], d3 = dinv[s3];
        float4 v0 = ld_half4(G + (size_t)s0 * (D / 2), lane);
        float4 v1 = ld_half4(G + (size_t)s1 * (D / 2), lane);
        float4 v2 = ld_half4(G + (size_t)s2 * (D / 2), lane);
        float4 v3 = ld_half4(G + (size_t)s3 * (D / 2), lane);
        acc.x += (v0.x * d0 + v1.x * d1) + (v2.x * d2 + v3.x * d3);
        acc.y += (v0.y * d0 + v1.y * d1) + (v2.y * d2 + v3.y * d3);
        acc.z += (v0.z * d0 + v1.z * d1) + (v2.z * d2 + v3.z * d3);
        acc.w += (v0.w * d0 + v1.w * d1) + (v2.w * d2 + v3.w * d3);
    }
    for (; e < end; e++) {
        int s = csr[e];
        float ds = dinv[s];
        float4 v = ld_half4(G + (size_t)s * (D / 2), lane);
        acc.x = fmaf(v.x, ds, acc.x); acc.y = fmaf(v.y, ds, acc.y);
        acc.z = fmaf(v.z, ds, acc.z); acc.w = fmaf(v.w, ds, acc.w);
    }

    float4 bb = ((const float4*)b)[lane];
    acc.x = fmaf(acc.x, dw, bb.x);
    acc.y = fmaf(acc.y, dw, bb.y);
    acc.z = fmaf(acc.z, dw, bb.z);
    acc.w = fmaf(acc.w, dw, bb.w);
    if (RELU) {
        acc.x = fmaxf(acc.x, 0.f); acc.y = fmaxf(acc.y, 0.f);
        acc.z = fmaxf(acc.z, 0.f); acc.w = fmaxf(acc.w, 0.f);
    }
    __half2 h0 = __float22half2_rn(make_float2(acc.x, acc.y));
    __half2 h1 = __float22half2_rn(make_float2(acc.z, acc.w));
    uint2 packed;
    packed.x = *(unsigned*)&h0;
    packed.y = *(unsigned*)&h1;
    ((uint2*)(Hout + (size_t)w * (D / 2)))[lane] = packed;
}

// ---------------- pair dot products on half2 embeddings ----------------
__global__ void __launch_bounds__(256)
k_pairs(const __half2* __restrict__ H, const int* __restrict__ pos,
        const int* __restrict__ neg, float* __restrict__ out, int P) {
    int gtid = blockIdx.x * blockDim.x + threadIdx.x;
    int w    = gtid >> 5;
    int lane = gtid & 31;
    if (w >= 2 * P) return;
    const int* pr = (w < P) ? pos : neg;
    int idx = (w < P) ? w : (w - P);
    int u = pr[2 * idx];
    int v = pr[2 * idx + 1];
    float4 a = ld_half4(H + (size_t)u * (D / 2), lane);
    float4 c = ld_half4(H + (size_t)v * (D / 2), lane);
    float s = a.x * c.x + a.y * c.y + a.z * c.z + a.w * c.w;
    #pragma unroll
    for (int o = 16; o; o >>= 1) s += __shfl_xor_sync(0xFFFFFFFFu, s, o);
    if (lane == 0) out[w] = s;
}

// ---------------- launch ----------------
template <typename T>
static inline T* symaddr(const void* sym) {
    void* p = nullptr;
    cudaGetSymbolAddress(&p, sym);
    return (T*)p;
}

extern "C" void kernel_launch(void* const* d_in, const int* in_sizes, int n_in,
                              void* d_out, int out_size) {
    const float* x  = (const float*)d_in[0];
    const float* W1 = (const float*)d_in[1];
    const float* b1 = (const float*)d_in[2];
    const float* W2 = (const float*)d_in[3];
    const float* b2 = (const float*)d_in[4];
    const int* eidx = (const int*)d_in[5];
    const int* ppos = (const int*)d_in[6];
    const int* pneg = (const int*)d_in[7];
    float* out = (float*)d_out;

    const int N = in_sizes[0] / D;
    const int E = in_sizes[5] / 2;
    const int P = in_sizes[6] / 2;
    const int* src = eidx;
    const int* dst = eidx + E;

    int*     cnt  = symaddr<int>(g_cnt);
    int*     off  = symaddr<int>(g_off);
    int*     cur  = symaddr<int>(g_cur);
    int*     csr  = symaddr<int>(g_csr);
    int*     bsum = symaddr<int>(g_bsum);
    float*   dinv = symaddr<float>(g_dinv);
    __half*  W2h  = symaddr<__half>(g_W2h);
    __half2* A    = symaddr<__half2>(g_A);
    __half2* B    = symaddr<__half2>(g_B);

    static bool s_init = false;
    static cudaStream_t s_side;
    static cudaEvent_t  ev_fork, ev_join;
    if (!s_init) {
        cudaStreamCreateWithFlags(&s_side, cudaStreamNonBlocking);
        cudaEventCreateWithFlags(&ev_fork, cudaEventDisableTiming);
        cudaEventCreateWithFlags(&ev_join, cudaEventDisableTiming);
        cudaFuncSetAttribute(k_gemm, cudaFuncAttributeMaxDynamicSharedMemorySize, GEMM_SMEM);
        s_init = true;
    }

    const int T = 256;
    int gridE     = (E + T - 1) / T;
    int nbScan    = (N + SCAN_BS - 1) / SCAN_BS;
    int gridGemm  = (N + GEMM_BM - 1) / GEMM_BM;
    int gridG2    = (N + 127) / 128;
    int gridGath  = (int)(((long long)N * 32 + T - 1) / T);
    int gridPairs = (int)(((long long)2 * P * 32 + T - 1) / T);

    // ---- fork: CSR build on side stream, concurrent with GEMM1 ----
    cudaEventRecord(ev_fork, 0);
    cudaStreamWaitEvent(s_side, ev_fork, 0);

    cudaMemsetAsync(cnt, 0, (size_t)N * sizeof(int), s_side);
    k_hist <<<gridE, T, 0, s_side>>>(cnt, dst, E);
    k_scan1<<<nbScan, SCAN_BS, 0, s_side>>>(cnt, off, bsum, dinv, N);
    k_scan3<<<nbScan, SCAN_BS, 0, s_side>>>(off, cur, bsum, N, E, nbScan);
    k_fill <<<gridE, T, 0, s_side>>>(src, dst, cur, csr, E);
    cudaEventRecord(ev_join, s_side);

    // ---- main: W2 convert + GEMM1 (X fp32 -> A half), join CSR ----
    k_w2h <<<(D * D + T - 1) / T, T>>>(W2, W2h);
    k_gemm<<<gridGemm, T, GEMM_SMEM>>>(x, W1, A, N);
    cudaStreamWaitEvent(0, ev_join, 0);

    // gather1: A(G1) -> B(H1), relu, half out
    k_gather<true><<<gridGath, T>>>(A, dinv, b1, B, off, csr, N);

    // GEMM2 (tensor cores): B(H1 half) @ W2h -> A(G2 half)
    k_gemm2_wmma<<<gridG2, T>>>((const __half*)B, W2h, (__half*)A, N);

    // gather2: A(G2) -> B(final H), no relu
    k_gather<false><<<gridGath, T>>>(A, dinv, b2, B, off, csr, N);

    // pairs on half embeddings
    k_pairs<<<gridPairs, T>>>(B, ppos, pneg, out, P);
}

// round 15
// speedup vs baseline: 1.3981x; 1.0840x over previous
#include <cuda_runtime.h>
#include <cuda_fp16.h>
#include <mma.h>
#include <cstdint>

using namespace nvcuda;

#define MAX_N 100000
#define MAX_E 1600000
#define D     128
#define SCAN_BS 1024

// ---------------- static device scratch ----------------
__device__ int     g_cnt [MAX_N];
__device__ int     g_off [MAX_N + 1];
__device__ int     g_cur [MAX_N];
__device__ int     g_csr [MAX_E];
__device__ int     g_bsum[256];
__device__ float   g_dinv[MAX_N];
__device__ __half  g_W1h[D * D];
__device__ __half  g_W2h[D * D];
__device__ __half2 g_A[(size_t)MAX_N * (D / 2)];   // G1, later G2
__device__ __half2 g_B[(size_t)MAX_N * (D / 2)];   // Xh, then H1, then final H

// ---------------- degree histogram (4 independent edges/thread for atomic MLP) ----------------
__global__ void k_hist(int* cnt, const int* __restrict__ dst, int E, int stride) {
    int base = blockIdx.x * blockDim.x + threadIdx.x;
    #pragma unroll
    for (int j = 0; j < 4; j++) {
        int e = base + j * stride;
        if (e < E) atomicAdd(&cnt[dst[e]], 1);
    }
}

// ---------------- scan pass 1: per-block exclusive scan (+dinv fused) ----------------
__global__ void k_scan1(const int* __restrict__ cnt, int* __restrict__ off,
                        int* __restrict__ bsum, float* __restrict__ dinv, int N) {
    __shared__ int sm[SCAN_BS];
    int i = blockIdx.x * SCAN_BS + threadIdx.x;
    int v = (i < N) ? cnt[i] : 0;
    if (i < N) dinv[i] = rsqrtf((float)(v + 1));   // +1 self loop
    sm[threadIdx.x] = v;
    __syncthreads();
    #pragma unroll
    for (int s = 1; s < SCAN_BS; s <<= 1) {
        int t = (threadIdx.x >= s) ? sm[threadIdx.x - s] : 0;
        __syncthreads();
        sm[threadIdx.x] += t;
        __syncthreads();
    }
    if (i < N) off[i] = sm[threadIdx.x] - v;
    if (threadIdx.x == SCAN_BS - 1) bsum[blockIdx.x] = sm[threadIdx.x];
}

// ---------------- scan pass 2: add block base (bsum scanned redundantly per block) ----------------
__global__ void k_scan3(int* __restrict__ off, int* __restrict__ cur,
                        const int* __restrict__ bsum, int N, int E, int nb) {
    __shared__ int sb[256];
    int t = threadIdx.x;
    if (t < 256) sb[t] = (t < nb) ? bsum[t] : 0;
    __syncthreads();
    #pragma unroll
    for (int s = 1; s < 256; s <<= 1) {
        int v = 0;
        if (t < 256 && t >= s) v = sb[t - s];
        __syncthreads();
        if (t < 256) sb[t] += v;
        __syncthreads();
    }
    int base = (blockIdx.x == 0) ? 0 : sb[blockIdx.x - 1];
    int i = blockIdx.x * SCAN_BS + t;
    if (i < N) {
        int o = off[i] + base;
        off[i] = o;
        cur[i] = o;
        if (i == N - 1) off[N] = E;
    }
}

// ---------------- CSR fill (4 independent edges/thread) ----------------
__global__ void k_fill(const int* __restrict__ src, const int* __restrict__ dst,
                       int* __restrict__ cur, int* __restrict__ csr, int E, int stride) {
    int base = blockIdx.x * blockDim.x + threadIdx.x;
    #pragma unroll
    for (int j = 0; j < 4; j++) {
        int e = base + j * stride;
        if (e < E) {
            int pos = atomicAdd(&cur[dst[e]], 1);
            csr[pos] = src[e];
        }
    }
}

// ---------------- weight fp32 -> fp16 (both weights in one launch) ----------------
__global__ void k_cvtw(const float* __restrict__ W1, const float* __restrict__ W2,
                       __half* __restrict__ W1h, __half* __restrict__ W2h) {
    int i = blockIdx.x * blockDim.x + threadIdx.x;
    if (i < D * D) {
        W1h[i] = __float2half(W1[i]);
        W2h[i] = __float2half(W2[i]);
    }
}

// ---------------- X fp32 -> fp16 (vectorized: float4 -> 4 halves) ----------------
__global__ void k_x2h(const float* __restrict__ X, __half* __restrict__ Xh, long long n4) {
    long long i = (long long)blockIdx.x * blockDim.x + threadIdx.x;
    if (i < n4) {
        float4 v = ((const float4*)X)[i];
        __half2 h0 = __float22half2_rn(make_float2(v.x, v.y));
        __half2 h1 = __float22half2_rn(make_float2(v.z, v.w));
        uint2 p;
        p.x = *(unsigned*)&h0;
        p.y = *(unsigned*)&h1;
        ((uint2*)Xh)[i] = p;
    }
}

// ---------------- WMMA GEMM: Out = Ah @ Wh  (half in/out, fp32 accum) ----------------
// 256 threads = 8 warps; 128 rows per CTA (16 rows per warp); full 128 cols.
__global__ void __launch_bounds__(256)
k_wmma(const __half* __restrict__ Ah, const __half* __restrict__ Wh,
       __half* __restrict__ Out, int N) {
    __shared__ __half ws[D * D];                 // 32 KB
    __shared__ float scratch[8][16 * 16];        // 8 KB
    int tid  = threadIdx.x;
    int wid  = tid >> 5;
    int lane = tid & 31;

    for (int i = tid; i < D * D / 8; i += 256)
        ((float4*)ws)[i] = ((const float4*)Wh)[i];
    __syncthreads();

    int row0 = blockIdx.x * 128 + wid * 16;
    if (row0 >= N) return;   // N % 16 == 0: warp tiles never straddle N

    wmma::fragment<wmma::accumulator, 16, 16, 16, float> c[8];
    #pragma unroll
    for (int n = 0; n < 8; n++) wmma::fill_fragment(c[n], 0.0f);

    #pragma unroll
    for (int k = 0; k < 8; k++) {
        wmma::fragment<wmma::matrix_a, 16, 16, 16, __half, wmma::row_major> a;
        wmma::load_matrix_sync(a, Ah + (size_t)row0 * D + k * 16, D);
        #pragma unroll
        for (int n = 0; n < 8; n++) {
            wmma::fragment<wmma::matrix_b, 16, 16, 16, __half, wmma::row_major> bf;
            wmma::load_matrix_sync(bf, ws + (k * 16) * D + n * 16, D);
            wmma::mma_sync(c[n], a, bf, c[n]);
        }
    }

    #pragma unroll
    for (int n = 0; n < 8; n++) {
        wmma::store_matrix_sync(scratch[wid], c[n], 16, wmma::mem_row_major);
        __syncwarp();
        #pragma unroll
        for (int j = 0; j < 8; j++) {
            int e = lane + j * 32;
            int r = e >> 4, col = e & 15;
            Out[(size_t)(row0 + r) * D + n * 16 + col] = __float2half(scratch[wid][e]);
        }
        __syncwarp();
    }
}

// ---------- CSR gather conv (half2 in, fp32 accumulate, half2 out) ----------
__device__ __forceinline__ float4 ld_half4(const __half2* row, int lane) {
    uint2 raw = ((const uint2*)row)[lane];
    __half2 p0 = *(__half2*)&raw.x;
    __half2 p1 = *(__half2*)&raw.y;
    float2 f0 = __half22float2(p0);
    float2 f1 = __half22float2(p1);
    return make_float4(f0.x, f0.y, f1.x, f1.y);
}

template <bool RELU>
__global__ void __launch_bounds__(256)
k_gather(const __half2* __restrict__ G, const float* __restrict__ dinv,
         const float* __restrict__ b, __half2* __restrict__ Hout,
         const int* __restrict__ off, const int* __restrict__ csr, int N) {
    int gtid = blockIdx.x * blockDim.x + threadIdx.x;
    int w    = gtid >> 5;
    int lane = gtid & 31;
    if (w >= N) return;

    float dw = dinv[w];
    float4 self = ld_half4(G + (size_t)w * (D / 2), lane);
    float4 acc  = make_float4(self.x * dw, self.y * dw, self.z * dw, self.w * dw);
    int e = off[w], end = off[w + 1];

    for (; e + 4 <= end; e += 4) {
        int s0 = csr[e], s1 = csr[e + 1], s2 = csr[e + 2], s3 = csr[e + 3];
        float d0 = dinv[s0], d1 = dinv[s1], d2 = dinv[s2], d3 = dinv[s3];
        float4 v0 = ld_half4(G + (size_t)s0 * (D / 2), lane);
        float4 v1 = ld_half4(G + (size_t)s1 * (D / 2), lane);
        float4 v2 = ld_half4(G + (size_t)s2 * (D / 2), lane);
        float4 v3 = ld_half4(G + (size_t)s3 * (D / 2), lane);
        acc.x += (v0.x * d0 + v1.x * d1) + (v2.x * d2 + v3.x * d3);
        acc.y += (v0.y * d0 + v1.y * d1) + (v2.y * d2 + v3.y * d3);
        acc.z += (v0.z * d0 + v1.z * d1) + (v2.z * d2 + v3.z * d3);
        acc.w += (v0.w * d0 + v1.w * d1) + (v2.w * d2 + v3.w * d3);
    }
    for (; e < end; e++) {
        int s = csr[e];
        float ds = dinv[s];
        float4 v = ld_half4(G + (size_t)s * (D / 2), lane);
        acc.x = fmaf(v.x, ds, acc.x); acc.y = fmaf(v.y, ds, acc.y);
        acc.z = fmaf(v.z, ds, acc.z); acc.w = fmaf(v.w, ds, acc.w);
    }

    float4 bb = ((const float4*)b)[lane];
    acc.x = fmaf(acc.x, dw, bb.x);
    acc.y = fmaf(acc.y, dw, bb.y);
    acc.z = fmaf(acc.z, dw, bb.z);
    acc.w = fmaf(acc.w, dw, bb.w);
    if (RELU) {
        acc.x = fmaxf(acc.x, 0.f); acc.y = fmaxf(acc.y, 0.f);
        acc.z = fmaxf(acc.z, 0.f); acc.w = fmaxf(acc.w, 0.f);
    }
    __half2 h0 = __float22half2_rn(make_float2(acc.x, acc.y));
    __half2 h1 = __float22half2_rn(make_float2(acc.z, acc.w));
    uint2 packed;
    packed.x = *(unsigned*)&h0;
    packed.y = *(unsigned*)&h1;
    ((uint2*)(Hout + (size_t)w * (D / 2)))[lane] = packed;
}

// ---------------- pair dot products on half2 embeddings ----------------
__global__ void __launch_bounds__(256)
k_pairs(const __half2* __restrict__ H, const int* __restrict__ pos,
        const int* __restrict__ neg, float* __restrict__ out, int P) {
    int gtid = blockIdx.x * blockDim.x + threadIdx.x;
    int w    = gtid >> 5;
    int lane = gtid & 31;
    if (w >= 2 * P) return;
    const int* pr = (w < P) ? pos : neg;
    int idx = (w < P) ? w : (w - P);
    int u = pr[2 * idx];
    int v = pr[2 * idx + 1];
    float4 a = ld_half4(H + (size_t)u * (D / 2), lane);
    float4 c = ld_half4(H + (size_t)v * (D / 2), lane);
    float s = a.x * c.x + a.y * c.y + a.z * c.z + a.w * c.w;
    #pragma unroll
    for (int o = 16; o; o >>= 1) s += __shfl_xor_sync(0xFFFFFFFFu, s, o);
    if (lane == 0) out[w] = s;
}

// ---------------- launch ----------------
template <typename T>
static inline T* symaddr(const void* sym) {
    void* p = nullptr;
    cudaGetSymbolAddress(&p, sym);
    return (T*)p;
}

extern "C" void kernel_launch(void* const* d_in, const int* in_sizes, int n_in,
                              void* d_out, int out_size) {
    const float* x  = (const float*)d_in[0];
    const float* W1 = (const float*)d_in[1];
    const float* b1 = (const float*)d_in[2];
    const float* W2 = (const float*)d_in[3];
    const float* b2 = (const float*)d_in[4];
    const int* eidx = (const int*)d_in[5];
    const int* ppos = (const int*)d_in[6];
    const int* pneg = (const int*)d_in[7];
    float* out = (float*)d_out;

    const int N = in_sizes[0] / D;
    const int E = in_sizes[5] / 2;
    const int P = in_sizes[6] / 2;
    const int* src = eidx;
    const int* dst = eidx + E;

    int*     cnt  = symaddr<int>(g_cnt);
    int*     off  = symaddr<int>(g_off);
    int*     cur  = symaddr<int>(g_cur);
    int*     csr  = symaddr<int>(g_csr);
    int*     bsum = symaddr<int>(g_bsum);
    float*   dinv = symaddr<float>(g_dinv);
    __half*  W1h  = symaddr<__half>(g_W1h);
    __half*  W2h  = symaddr<__half>(g_W2h);
    __half2* A    = symaddr<__half2>(g_A);
    __half2* B    = symaddr<__half2>(g_B);

    static bool s_init = false;
    static cudaStream_t s_side;
    static cudaEvent_t  ev_fork, ev_join;
    if (!s_init) {
        cudaStreamCreateWithFlags(&s_side, cudaStreamNonBlocking);
        cudaEventCreateWithFlags(&ev_fork, cudaEventDisableTiming);
        cudaEventCreateWithFlags(&ev_join, cudaEventDisableTiming);
        s_init = true;
    }

    const int T = 256;
    int strideE   = ((E + 3) / 4 + T - 1) / T * T;          // edges per j-step
    int gridE4    = (strideE + T - 1) / T;                  // blocks for 4-edge kernels
    int nbScan    = (N + SCAN_BS - 1) / SCAN_BS;
    int gridWmma  = (N + 127) / 128;
    int gridGath  = (int)(((long long)N * 32 + T - 1) / T);
    int gridPairs = (int)(((long long)2 * P * 32 + T - 1) / T);
    long long n4  = (long long)N * 32;                      // float4 count of X
    int gridX     = (int)((n4 + T - 1) / T);

    // ---- fork: CSR build on side stream, concurrent with conversions + GEMM1 ----
    cudaEventRecord(ev_fork, 0);
    cudaStreamWaitEvent(s_side, ev_fork, 0);

    cudaMemsetAsync(cnt, 0, (size_t)N * sizeof(int), s_side);
    k_hist <<<gridE4, T, 0, s_side>>>(cnt, dst, E, strideE);
    k_scan1<<<nbScan, SCAN_BS, 0, s_side>>>(cnt, off, bsum, dinv, N);
    k_scan3<<<nbScan, SCAN_BS, 0, s_side>>>(off, cur, bsum, N, E, nbScan);
    k_fill <<<gridE4, T, 0, s_side>>>(src, dst, cur, csr, E, strideE);
    cudaEventRecord(ev_join, s_side);

    // ---- main: convert weights + X, GEMM1 (tensor cores), join CSR ----
    k_cvtw<<<(D * D + T - 1) / T, T>>>(W1, W2, W1h, W2h);
    k_x2h <<<gridX, T>>>(x, (__half*)B, n4);                 // Xh lives in B
    k_wmma<<<gridWmma, T>>>((const __half*)B, W1h, (__half*)A, N);   // G1 -> A
    cudaStreamWaitEvent(0, ev_join, 0);

    // gather1: A(G1) -> B(H1), relu  (overwrites Xh, already consumed)
    k_gather<true><<<gridGath, T>>>(A, dinv, b1, B, off, csr, N);

    // GEMM2: B(H1) @ W2h -> A(G2)
    k_wmma<<<gridWmma, T>>>((const __half*)B, W2h, (__half*)A, N);

    // gather2: A(G2) -> B(final H), no relu
    k_gather<false><<<gridGath, T>>>(A, dinv, b2, B, off, csr, N);

    // pairs on half embeddings
    k_pairs<<<gridPairs, T>>>(B, ppos, pneg, out, P);
}